// round 1
// baseline (speedup 1.0000x reference)
#include <cuda_runtime.h>

// ---------------------------------------------------------------------------
// T6 Tensor-Product Attention, fp32 baseline with packed f32x2 FMA everywhere.
// B=2, S=2048, D=1024, H=16, DK=64, Q_RANK=6, RANK=2, causal.
// ---------------------------------------------------------------------------

#define NB 2
#define NS 2048
#define ND 1024
#define NH 16
#define DKH 64
#define QR 6
#define RK 2
#define NT (NB * NS)  // 4096 tokens

// Scratch (device globals; allocation is forbidden)
__device__ float g_Aq[NT * NH * QR];   // 4096 x 96
__device__ float g_Bq[NT * QR * DKH];  // 4096 x 384
__device__ float g_Ak[NT * NH * RK];   // 4096 x 32
__device__ float g_Bk[NT * RK * DKH];  // 4096 x 128
__device__ float g_Av[NT * NH * RK];
__device__ float g_Bv[NT * RK * DKH];
__device__ float g_qh[(size_t)NB * NH * NS * DKH];  // (b,h,s,d)
__device__ float g_kh[(size_t)NB * NH * NS * DKH];
__device__ float g_vh[(size_t)NB * NH * NS * DKH];
__device__ float g_att[(size_t)NT * ND];            // (b,s,h*dk)

// ---- packed f32x2 helpers (FFMA2: 2x fp32 FMA throughput on sm_103a) ------
__device__ __forceinline__ unsigned long long pk2(float x, float y) {
    unsigned long long r;
    asm("mov.b64 %0, {%1, %2};" : "=l"(r) : "f"(x), "f"(y));
    return r;
}
__device__ __forceinline__ void upk2(unsigned long long v, float& x, float& y) {
    asm("mov.b64 {%0, %1}, %2;" : "=f"(x), "=f"(y) : "l"(v));
}
__device__ __forceinline__ void ffma2(unsigned long long& d, unsigned long long a,
                                      unsigned long long b) {
    asm("fma.rn.f32x2 %0, %1, %2, %0;" : "+l"(d) : "l"(a), "l"(b));
}
__device__ __forceinline__ void fmul2(unsigned long long& d, unsigned long long a) {
    asm("mul.rn.f32x2 %0, %0, %1;" : "+l"(d) : "l"(a));
}

// ---------------------------------------------------------------------------
// Generic row-major fp32 GEMM: C[M,N] = X[M,K] * W[K,N]
// 64x64 tile, BK=32, 256 threads, 4x4 microtile (f32x2 accumulators).
// Requires: M % 64 == 0, K % 32 == 0, N % 4 == 0.
// ---------------------------------------------------------------------------
__global__ __launch_bounds__(256) void gemm_k(const float* __restrict__ X,
                                              const float* __restrict__ W,
                                              float* __restrict__ C,
                                              int M, int N, int K) {
    __shared__ float Xs[32][64];  // [k][m] (transposed)
    __shared__ float Ws[32][64];  // [k][n]
    const int t = threadIdx.x;
    const int tx = t & 15;
    const int ty = t >> 4;
    const int m0 = blockIdx.y * 64;
    const int n0 = blockIdx.x * 64;

    unsigned long long acc[4][2];
#pragma unroll
    for (int i = 0; i < 4; i++) { acc[i][0] = 0ull; acc[i][1] = 0ull; }

    for (int k0 = 0; k0 < K; k0 += 32) {
#pragma unroll
        for (int rep = 0; rep < 2; rep++) {
            int idx = t + rep * 256;
            // X tile: 64 rows x 8 float4
            int row = idx >> 3;
            int c4 = (idx & 7) * 4;
            float4 vx = *(const float4*)&X[(size_t)(m0 + row) * K + k0 + c4];
            Xs[c4 + 0][row] = vx.x;
            Xs[c4 + 1][row] = vx.y;
            Xs[c4 + 2][row] = vx.z;
            Xs[c4 + 3][row] = vx.w;
            // W tile: 32 rows x 16 float4
            int r = idx >> 4;
            int wc = (idx & 15) * 4;
            float4 vw = make_float4(0.f, 0.f, 0.f, 0.f);
            int gn = n0 + wc;
            if (gn < N) vw = *(const float4*)&W[(size_t)(k0 + r) * N + gn];
            *(float4*)&Ws[r][wc] = vw;
        }
        __syncthreads();
#pragma unroll
        for (int kk = 0; kk < 32; kk++) {
            float4 a = *(const float4*)&Xs[kk][ty * 4];
            ulonglong2 bb = *(const ulonglong2*)&Ws[kk][tx * 4];
            unsigned long long a0 = pk2(a.x, a.x), a1 = pk2(a.y, a.y),
                               a2 = pk2(a.z, a.z), a3 = pk2(a.w, a.w);
            ffma2(acc[0][0], a0, bb.x); ffma2(acc[0][1], a0, bb.y);
            ffma2(acc[1][0], a1, bb.x); ffma2(acc[1][1], a1, bb.y);
            ffma2(acc[2][0], a2, bb.x); ffma2(acc[2][1], a2, bb.y);
            ffma2(acc[3][0], a3, bb.x); ffma2(acc[3][1], a3, bb.y);
        }
        __syncthreads();
    }

#pragma unroll
    for (int i = 0; i < 4; i++) {
        int gm = m0 + ty * 4 + i;
#pragma unroll
        for (int j = 0; j < 2; j++) {
            int gn = n0 + tx * 4 + j * 2;
            if (gn < N) {
                float x, y;
                upk2(acc[i][j], x, y);
                C[(size_t)gm * N + gn] = x;
                C[(size_t)gm * N + gn + 1] = y;
            }
        }
    }
}

// ---------------------------------------------------------------------------
// RoPE + rank contraction: builds qh/kh/vh in (b,h,s,d) layout.
// Folds softmax scale 1/DK into qh together with 1/Q_RANK; kh,vh get 1/RANK.
// One block per token, 128 threads.
// ---------------------------------------------------------------------------
__global__ __launch_bounds__(128) void mix_k() {
    const int t = blockIdx.x;
    const int b = t >> 11;
    const int s = t & (NS - 1);
    const int tid = threadIdx.x;

    __shared__ float sAq[NH * QR];   // 96
    __shared__ float sAk[NH * RK];   // 32
    __shared__ float sAv[NH * RK];   // 32
    __shared__ float sBq[QR * DKH];  // 384
    __shared__ float sBk[RK * DKH];  // 128
    __shared__ float sBv[RK * DKH];  // 128

    if (tid < 96) sAq[tid] = g_Aq[t * 96 + tid];
    if (tid < 32) {
        sAk[tid] = g_Ak[t * 32 + tid];
        sAv[tid] = g_Av[t * 32 + tid];
    }
    for (int i = tid; i < 384; i += 128) sBq[i] = g_Bq[t * 384 + i];
    sBk[tid] = g_Bk[t * 128 + tid];
    sBv[tid] = g_Bv[t * 128 + tid];
    __syncthreads();

    // RoPE on sBq (6 rows) and sBk (2 rows): 8 rows x 32 pairs = 256 items
    for (int i = tid; i < (QR + RK) * 32; i += 128) {
        int r = i >> 5;
        int dd = i & 31;
        // match jax fp32 recipe: fp32 inv_freq, fp32 angle, accurate sincos
        float inv = (float)pow(10000.0, -(double)dd / 32.0);
        float ang = (float)s * inv;
        float c, sn;
        sincosf(ang, &sn, &c);
        float* base = (r < QR) ? &sBq[r * DKH] : &sBk[(r - QR) * DKH];
        float x1 = base[dd];
        float x2 = base[dd + 32];
        base[dd] = x1 * c + x2 * sn;
        base[dd + 32] = -x1 * sn + x2 * c;
    }
    __syncthreads();

    const float qsc = 1.f / (6.f * 64.f);
    for (int i = tid; i < NH * DKH; i += 128) {
        int h = i >> 6;
        int d = i & 63;
        float aq = 0.f;
#pragma unroll
        for (int r = 0; r < QR; r++) aq += sAq[h * QR + r] * sBq[r * DKH + d];
        size_t o = (((size_t)b * NH + h) * NS + s) * DKH + d;
        g_qh[o] = aq * qsc;
        float ak = sAk[h * RK + 0] * sBk[d] + sAk[h * RK + 1] * sBk[DKH + d];
        g_kh[o] = ak * 0.5f;
        float av = sAv[h * RK + 0] * sBv[d] + sAv[h * RK + 1] * sBv[DKH + d];
        g_vh[o] = av * 0.5f;
    }
}

// ---------------------------------------------------------------------------
// Causal flash attention: 64x64 tiles, fp32, f32x2 FMA, online softmax.
// grid = (S/64, H, B), 256 threads, 64KB dynamic smem.
// Writes g_att in (b, s, h, d) layout for the output projection.
// ---------------------------------------------------------------------------
__global__ __launch_bounds__(256) void attn_k() {
    extern __shared__ float sm[];
    float* Qt = sm;                // [d][q]  (transposed)
    float* Kt = sm + 64 * 64;      // [d][k]  (transposed)
    float* Vs = sm + 2 * 64 * 64;  // [k][d]
    float* Pt = sm + 3 * 64 * 64;  // [k][q]  (transposed)

    const int qt = blockIdx.x;
    const int h = blockIdx.y;
    const int b = blockIdx.z;
    const int tid = threadIdx.x;
    const int tx = tid & 15;
    const int ty = tid >> 4;
    const size_t bh = ((size_t)b * NH + h) * NS * DKH;

#pragma unroll
    for (int rep = 0; rep < 4; rep++) {
        int idx = tid + rep * 256;
        int qq = idx >> 4;
        int d4 = (idx & 15) * 4;
        float4 vq = *(const float4*)&g_qh[bh + (size_t)(qt * 64 + qq) * DKH + d4];
        Qt[(d4 + 0) * 64 + qq] = vq.x;
        Qt[(d4 + 1) * 64 + qq] = vq.y;
        Qt[(d4 + 2) * 64 + qq] = vq.z;
        Qt[(d4 + 3) * 64 + qq] = vq.w;
    }

    float m[4] = {-1e30f, -1e30f, -1e30f, -1e30f};
    float l[4] = {0.f, 0.f, 0.f, 0.f};
    unsigned long long o2[4][2];
#pragma unroll
    for (int i = 0; i < 4; i++) { o2[i][0] = 0ull; o2[i][1] = 0ull; }

    __syncthreads();

    for (int kt = 0; kt <= qt; kt++) {
#pragma unroll
        for (int rep = 0; rep < 4; rep++) {
            int idx = tid + rep * 256;
            int kk = idx >> 4;
            int d4 = (idx & 15) * 4;
            float4 vk = *(const float4*)&g_kh[bh + (size_t)(kt * 64 + kk) * DKH + d4];
            Kt[(d4 + 0) * 64 + kk] = vk.x;
            Kt[(d4 + 1) * 64 + kk] = vk.y;
            Kt[(d4 + 2) * 64 + kk] = vk.z;
            Kt[(d4 + 3) * 64 + kk] = vk.w;
            float4 vv = *(const float4*)&g_vh[bh + (size_t)(kt * 64 + kk) * DKH + d4];
            *(float4*)&Vs[kk * 64 + d4] = vv;
        }
        __syncthreads();

        // S = Q * K^T  (64x64, inner dim DKH)
        unsigned long long s2[4][2];
#pragma unroll
        for (int i = 0; i < 4; i++) { s2[i][0] = 0ull; s2[i][1] = 0ull; }
#pragma unroll 8
        for (int d = 0; d < 64; d++) {
            float4 a = *(const float4*)&Qt[d * 64 + ty * 4];
            ulonglong2 bb = *(const ulonglong2*)&Kt[d * 64 + tx * 4];
            unsigned long long a0 = pk2(a.x, a.x), a1 = pk2(a.y, a.y),
                               a2 = pk2(a.z, a.z), a3 = pk2(a.w, a.w);
            ffma2(s2[0][0], a0, bb.x); ffma2(s2[0][1], a0, bb.y);
            ffma2(s2[1][0], a1, bb.x); ffma2(s2[1][1], a1, bb.y);
            ffma2(s2[2][0], a2, bb.x); ffma2(s2[2][1], a2, bb.y);
            ffma2(s2[3][0], a3, bb.x); ffma2(s2[3][1], a3, bb.y);
        }

        float sv[4][4];
#pragma unroll
        for (int i = 0; i < 4; i++) {
            upk2(s2[i][0], sv[i][0], sv[i][1]);
            upk2(s2[i][1], sv[i][2], sv[i][3]);
        }
        if (kt == qt) {
#pragma unroll
            for (int i = 0; i < 4; i++)
#pragma unroll
                for (int j = 0; j < 4; j++)
                    if (tx * 4 + j > ty * 4 + i) sv[i][j] = -1e30f;
        }

        // online softmax (rows = ty*4+i; reduce over 16-lane tx groups)
#pragma unroll
        for (int i = 0; i < 4; i++) {
            float mx = fmaxf(fmaxf(sv[i][0], sv[i][1]), fmaxf(sv[i][2], sv[i][3]));
#pragma unroll
            for (int off = 1; off < 16; off <<= 1)
                mx = fmaxf(mx, __shfl_xor_sync(0xffffffffu, mx, off));
            float mn = fmaxf(m[i], mx);
            float corr = __expf(m[i] - mn);
            float rs = 0.f;
#pragma unroll
            for (int j = 0; j < 4; j++) {
                sv[i][j] = __expf(sv[i][j] - mn);
                rs += sv[i][j];
            }
#pragma unroll
            for (int off = 1; off < 16; off <<= 1)
                rs += __shfl_xor_sync(0xffffffffu, rs, off);
            l[i] = l[i] * corr + rs;
            m[i] = mn;
            unsigned long long cc = pk2(corr, corr);
            fmul2(o2[i][0], cc);
            fmul2(o2[i][1], cc);
#pragma unroll
            for (int j = 0; j < 4; j++)
                Pt[(tx * 4 + j) * 64 + ty * 4 + i] = sv[i][j];
        }
        __syncthreads();

        // O += P * V (inner dim = 64 keys)
#pragma unroll 8
        for (int kk = 0; kk < 64; kk++) {
            float4 a = *(const float4*)&Pt[kk * 64 + ty * 4];
            ulonglong2 bb = *(const ulonglong2*)&Vs[kk * 64 + tx * 4];
            unsigned long long a0 = pk2(a.x, a.x), a1 = pk2(a.y, a.y),
                               a2 = pk2(a.z, a.z), a3 = pk2(a.w, a.w);
            ffma2(o2[0][0], a0, bb.x); ffma2(o2[0][1], a0, bb.y);
            ffma2(o2[1][0], a1, bb.x); ffma2(o2[1][1], a1, bb.y);
            ffma2(o2[2][0], a2, bb.x); ffma2(o2[2][1], a2, bb.y);
            ffma2(o2[3][0], a3, bb.x); ffma2(o2[3][1], a3, bb.y);
        }
        __syncthreads();
    }

#pragma unroll
    for (int i = 0; i < 4; i++) {
        float inv = 1.f / l[i];
        int qg = qt * 64 + ty * 4 + i;
        size_t ob = (((size_t)b * NS + qg) * NH + h) * DKH + tx * 4;
        float x, y;
        upk2(o2[i][0], x, y);
        g_att[ob + 0] = x * inv;
        g_att[ob + 1] = y * inv;
        upk2(o2[i][1], x, y);
        g_att[ob + 2] = x * inv;
        g_att[ob + 3] = y * inv;
    }
}

// ---------------------------------------------------------------------------
extern "C" void kernel_launch(void* const* d_in, const int* in_sizes, int n_in,
                              void* d_out, int out_size) {
    (void)in_sizes; (void)n_in; (void)out_size;
    const float* q = (const float*)d_in[0];
    const float* k = (const float*)d_in[1];
    const float* v = (const float*)d_in[2];
    // d_in[3] = mask (causal, known statically)
    const float* W_Aq = (const float*)d_in[4];
    const float* W_Ak = (const float*)d_in[5];
    const float* W_Av = (const float*)d_in[6];
    const float* W_Bq = (const float*)d_in[7];
    const float* W_Bk = (const float*)d_in[8];
    const float* W_Bv = (const float*)d_in[9];
    const float* Wo = (const float*)d_in[10];

    float *pAq, *pBq, *pAk, *pBk, *pAv, *pBv, *pAtt;
    cudaGetSymbolAddress((void**)&pAq, g_Aq);
    cudaGetSymbolAddress((void**)&pBq, g_Bq);
    cudaGetSymbolAddress((void**)&pAk, g_Ak);
    cudaGetSymbolAddress((void**)&pBk, g_Bk);
    cudaGetSymbolAddress((void**)&pAv, g_Av);
    cudaGetSymbolAddress((void**)&pBv, g_Bv);
    cudaGetSymbolAddress((void**)&pAtt, g_att);

    // projections
    gemm_k<<<dim3(2, NT / 64), 256>>>(q, W_Aq, pAq, NT, NH * QR, ND);
    gemm_k<<<dim3(6, NT / 64), 256>>>(q, W_Bq, pBq, NT, QR * DKH, ND);
    gemm_k<<<dim3(1, NT / 64), 256>>>(k, W_Ak, pAk, NT, NH * RK, ND);
    gemm_k<<<dim3(2, NT / 64), 256>>>(k, W_Bk, pBk, NT, RK * DKH, ND);
    gemm_k<<<dim3(1, NT / 64), 256>>>(v, W_Av, pAv, NT, NH * RK, ND);
    gemm_k<<<dim3(2, NT / 64), 256>>>(v, W_Bv, pBv, NT, RK * DKH, ND);

    // rope + rank contraction
    mix_k<<<NT, 128>>>();

    // causal flash attention (64KB dynamic smem)
    cudaFuncSetAttribute(attn_k, cudaFuncAttributeMaxDynamicSharedMemorySize,
                         4 * 64 * 64 * (int)sizeof(float));
    attn_k<<<dim3(NS / 64, NH, NB), 256, 4 * 64 * 64 * sizeof(float)>>>();

    // output projection -> d_out
    gemm_k<<<dim3(ND / 64, NT / 64), 256>>>(pAtt, Wo, (float*)d_out, NT, ND, ND);
}

// round 2
// speedup vs baseline: 2.1587x; 2.1587x over previous
#include <cuda_runtime.h>

// ---------------------------------------------------------------------------
// T6 Tensor-Product Attention — tf32 mma.sync everywhere, fp32 accumulate.
// B=2, S=2048, D=1024, H=16, DK=64, Q_RANK=6, RANK=2, causal.
// ---------------------------------------------------------------------------

#define NB 2
#define NS 2048
#define ND 1024
#define NH 16
#define DKH 64
#define QR 6
#define RK 2
#define NT (NB * NS)  // 4096 tokens

// Scratch (device globals; allocation is forbidden)
__device__ float g_Aq[NT * 96];
__device__ float g_Bq[NT * 384];
__device__ float g_Ak[NT * 32];
__device__ float g_Bk[NT * 128];
__device__ float g_Av[NT * 32];
__device__ float g_Bv[NT * 128];
__device__ float g_qh[(size_t)NB * NH * NS * DKH];  // (b,h,s,d), tf32-rounded
__device__ float g_kh[(size_t)NB * NH * NS * DKH];
__device__ float g_vh[(size_t)NB * NH * NS * DKH];
__device__ float g_att[(size_t)NT * ND];            // (b,s,h*dk)

__device__ __forceinline__ float to_tf32(float x) {
    asm("cvt.rna.tf32.f32 %0, %0;" : "+f"(x));
    return x;
}
__device__ __forceinline__ unsigned fu(float x) { return __float_as_uint(x); }

// C[16x8] += A[16x8] * B[8x8], tf32 inputs, fp32 accum
__device__ __forceinline__ void mma8(float* c, const unsigned* a, const unsigned* b) {
    asm("mma.sync.aligned.m16n8k8.row.col.f32.tf32.tf32.f32 "
        "{%0,%1,%2,%3},{%4,%5,%6,%7},{%8,%9},{%0,%1,%2,%3};"
        : "+f"(c[0]), "+f"(c[1]), "+f"(c[2]), "+f"(c[3])
        : "r"(a[0]), "r"(a[1]), "r"(a[2]), "r"(a[3]), "r"(b[0]), "r"(b[1]));
}

// ---------------------------------------------------------------------------
// Generic tf32 GEMM body: C[m0:+128, n0:+64] = X[M,K] * W[K,N] tile.
// 256 threads = 8 warps (4 m x 2 n), warp tile 32x32, BK=32.
// Xs stride 36 (== 4 mod 32: conflict-free A-frag LDS);
// Ws stride 72 (== 8 mod 32: conflict-free B-frag LDS).
// Requires K % 32 == 0, N % 32 == 0, rows m0..m0+127 valid.
// ---------------------------------------------------------------------------
#define XS_STR 36
#define WS_STR 72

__device__ __forceinline__ void gemm_body(const float* __restrict__ X,
                                          const float* __restrict__ W,
                                          float* __restrict__ C, int N, int K,
                                          int m0, int n0, float* Xs, float* Ws) {
    const int tid = threadIdx.x;
    const int lane = tid & 31, wid = tid >> 5;
    const int g = lane >> 2, qd = lane & 3;
    const int wm = (wid & 3) * 32, wn = (wid >> 2) * 32;

    float acc[2][4][4];
#pragma unroll
    for (int mt = 0; mt < 2; mt++)
#pragma unroll
        for (int nt = 0; nt < 4; nt++)
#pragma unroll
            for (int j = 0; j < 4; j++) acc[mt][nt][j] = 0.f;

    for (int k0 = 0; k0 < K; k0 += 32) {
#pragma unroll
        for (int i = 0; i < 4; i++) {  // X tile 128x32 = 1024 float4
            int idx = tid + i * 256;
            int row = idx >> 3, c = (idx & 7) * 4;
            float4 vx = *(const float4*)&X[(size_t)(m0 + row) * K + k0 + c];
            vx.x = to_tf32(vx.x); vx.y = to_tf32(vx.y);
            vx.z = to_tf32(vx.z); vx.w = to_tf32(vx.w);
            *(float4*)&Xs[row * XS_STR + c] = vx;
        }
#pragma unroll
        for (int i = 0; i < 2; i++) {  // W tile 32x64 = 512 float4
            int idx = tid + i * 256;
            int r = idx >> 4, c = (idx & 15) * 4;
            int gn = n0 + c;
            float4 vw = make_float4(0.f, 0.f, 0.f, 0.f);
            if (gn < N) vw = *(const float4*)&W[(size_t)(k0 + r) * N + gn];
            vw.x = to_tf32(vw.x); vw.y = to_tf32(vw.y);
            vw.z = to_tf32(vw.z); vw.w = to_tf32(vw.w);
            *(float4*)&Ws[r * WS_STR + c] = vw;
        }
        __syncthreads();
#pragma unroll
        for (int ks = 0; ks < 4; ks++) {
            unsigned a[2][4], b[4][2];
#pragma unroll
            for (int mt = 0; mt < 2; mt++) {
                int rb = wm + mt * 16;
                int cb = ks * 8 + qd;
                a[mt][0] = fu(Xs[(rb + g) * XS_STR + cb]);
                a[mt][1] = fu(Xs[(rb + 8 + g) * XS_STR + cb]);
                a[mt][2] = fu(Xs[(rb + g) * XS_STR + cb + 4]);
                a[mt][3] = fu(Xs[(rb + 8 + g) * XS_STR + cb + 4]);
            }
#pragma unroll
            for (int nt = 0; nt < 4; nt++) {
                int nn = wn + nt * 8 + g;
                b[nt][0] = fu(Ws[(ks * 8 + qd) * WS_STR + nn]);
                b[nt][1] = fu(Ws[(ks * 8 + qd + 4) * WS_STR + nn]);
            }
#pragma unroll
            for (int mt = 0; mt < 2; mt++)
#pragma unroll
                for (int nt = 0; nt < 4; nt++) mma8(acc[mt][nt], a[mt], b[nt]);
        }
        __syncthreads();
    }

#pragma unroll
    for (int mt = 0; mt < 2; mt++)
#pragma unroll
        for (int nt = 0; nt < 4; nt++) {
            int row = m0 + wm + mt * 16 + g;
            int col = n0 + wn + nt * 8 + 2 * qd;
            if (col < N) {
                *(float2*)&C[(size_t)row * N + col] =
                    make_float2(acc[mt][nt][0], acc[mt][nt][1]);
                *(float2*)&C[(size_t)(row + 8) * N + col] =
                    make_float2(acc[mt][nt][2], acc[mt][nt][3]);
            }
        }
}

// Standalone GEMM (used for the Wo projection)
__global__ __launch_bounds__(256) void gemm_k(const float* __restrict__ X,
                                              const float* __restrict__ W,
                                              float* __restrict__ C, int N, int K) {
    __shared__ float Xs[128 * XS_STR];
    __shared__ float Ws[32 * WS_STR];
    gemm_body(X, W, C, N, K, blockIdx.y * 128, blockIdx.x * 64, Xs, Ws);
}

// All 6 skinny projections in one launch. grid = (14 col-slots, 32 row-tiles).
__global__ __launch_bounds__(256) void proj_k(const float* __restrict__ q,
                                              const float* __restrict__ k,
                                              const float* __restrict__ v,
                                              const float* __restrict__ WAq,
                                              const float* __restrict__ WBq,
                                              const float* __restrict__ WAk,
                                              const float* __restrict__ WBk,
                                              const float* __restrict__ WAv,
                                              const float* __restrict__ WBv) {
    __shared__ float Xs[128 * XS_STR];
    __shared__ float Ws[32 * WS_STR];
    const int slot = blockIdx.x;
    const int slot_seg[14] = {0, 0, 1, 1, 1, 1, 1, 1, 2, 3, 3, 4, 5, 5};
    const int slot_n0[14] = {0, 64, 0, 64, 128, 192, 256, 320, 0, 0, 64, 0, 0, 64};
    const int seg = slot_seg[slot];
    const int seg_N[6] = {96, 384, 32, 128, 32, 128};
    const float* Xp = (seg < 2) ? q : (seg < 4) ? k : v;
    const float* Wp;
    float* Cp;
    switch (seg) {
        case 0: Wp = WAq; Cp = g_Aq; break;
        case 1: Wp = WBq; Cp = g_Bq; break;
        case 2: Wp = WAk; Cp = g_Ak; break;
        case 3: Wp = WBk; Cp = g_Bk; break;
        case 4: Wp = WAv; Cp = g_Av; break;
        default: Wp = WBv; Cp = g_Bv; break;
    }
    gemm_body(Xp, Wp, Cp, seg_N[seg], ND, blockIdx.y * 128, slot_n0[slot], Xs, Ws);
}

// ---------------------------------------------------------------------------
// RoPE + rank contraction -> qh/kh/vh (b,h,s,d), tf32-rounded.
// Folds 1/(Q_RANK*DK) into qh and 1/RANK into kh, vh.
// ---------------------------------------------------------------------------
__global__ __launch_bounds__(128) void mix_k() {
    const int t = blockIdx.x;
    const int b = t >> 11;
    const int s = t & (NS - 1);
    const int tid = threadIdx.x;

    __shared__ float sAq[96], sAk[32], sAv[32];
    __shared__ float sBq[384], sBk[128], sBv[128];

    if (tid < 96) sAq[tid] = g_Aq[t * 96 + tid];
    if (tid < 32) {
        sAk[tid] = g_Ak[t * 32 + tid];
        sAv[tid] = g_Av[t * 32 + tid];
    }
    for (int i = tid; i < 384; i += 128) sBq[i] = g_Bq[t * 384 + i];
    sBk[tid] = g_Bk[t * 128 + tid];
    sBv[tid] = g_Bv[t * 128 + tid];
    __syncthreads();

    for (int i = tid; i < (QR + RK) * 32; i += 128) {
        int r = i >> 5;
        int dd = i & 31;
        float inv = (float)pow(10000.0, -(double)dd / 32.0);
        float ang = (float)s * inv;
        float c, sn;
        sincosf(ang, &sn, &c);
        float* base = (r < QR) ? &sBq[r * DKH] : &sBk[(r - QR) * DKH];
        float x1 = base[dd];
        float x2 = base[dd + 32];
        base[dd] = x1 * c + x2 * sn;
        base[dd + 32] = -x1 * sn + x2 * c;
    }
    __syncthreads();

    const float qsc = 1.f / (6.f * 64.f);
    for (int i = tid; i < NH * DKH; i += 128) {
        int h = i >> 6;
        int d = i & 63;
        float aq = 0.f;
#pragma unroll
        for (int r = 0; r < QR; r++) aq += sAq[h * QR + r] * sBq[r * DKH + d];
        size_t o = (((size_t)b * NH + h) * NS + s) * DKH + d;
        g_qh[o] = to_tf32(aq * qsc);
        float ak = sAk[h * RK + 0] * sBk[d] + sAk[h * RK + 1] * sBk[DKH + d];
        g_kh[o] = to_tf32(ak * 0.5f);
        float av = sAv[h * RK + 0] * sBv[d] + sAv[h * RK + 1] * sBv[DKH + d];
        g_vh[o] = to_tf32(av * 0.5f);
    }
}

// ---------------------------------------------------------------------------
// Causal flash attention, tf32 mma. Q tile 128, KV tile 64.
// 8 warps, each warp: 16 q rows x 64 kv cols (m16 x 8 n-tiles, k in 8-steps).
// Smem strides: A-pattern arrays (Qs, Ks, Ps) 68 (==4 mod 32);
//               B-pattern with k in row dim (Vs) 72 (==8 mod 32).
// ---------------------------------------------------------------------------
#define QS_STR 68
#define KS_STR 68
#define VS_STR 72
#define PS_STR 68
#define ATT_SMEM ((128 * QS_STR + 64 * KS_STR + 64 * VS_STR + 128 * PS_STR) * 4)

__global__ __launch_bounds__(256) void attn_k() {
    extern __shared__ float sm[];
    float* Qs = sm;                     // [q][d]   128 x 68
    float* Ks = Qs + 128 * QS_STR;      // [key][d]  64 x 68
    float* Vs = Ks + 64 * KS_STR;       // [key][d]  64 x 72
    float* Ps = Vs + 64 * VS_STR;       // [q][key] 128 x 68

    const int qt = blockIdx.x, h = blockIdx.y, b = blockIdx.z;
    const int q0 = qt * 128;
    const int tid = threadIdx.x, lane = tid & 31, wid = tid >> 5;
    const int g = lane >> 2, qd = lane & 3;
    const size_t bh = ((size_t)b * NH + h) * NS * DKH;
    const int rb = wid * 16;  // warp's q-row base within the tile

#pragma unroll
    for (int i = 0; i < 8; i++) {  // Q tile 128x64 = 2048 float4
        int idx = tid + i * 256;
        int row = idx >> 4, c = (idx & 15) * 4;
        *(float4*)&Qs[row * QS_STR + c] =
            *(const float4*)&g_qh[bh + (size_t)(q0 + row) * DKH + c];
    }

    float m2[2] = {-1e30f, -1e30f};
    float l2[2] = {0.f, 0.f};
    float o[8][4];
#pragma unroll
    for (int nt = 0; nt < 8; nt++)
#pragma unroll
        for (int j = 0; j < 4; j++) o[nt][j] = 0.f;

    __syncthreads();

    const int nkt = 2 * qt + 2;
    for (int kt = 0; kt < nkt; kt++) {
#pragma unroll
        for (int i = 0; i < 4; i++) {  // K,V tiles 64x64 each
            int idx = tid + i * 256;
            int row = idx >> 4, c = (idx & 15) * 4;
            size_t go = bh + (size_t)(kt * 64 + row) * DKH + c;
            *(float4*)&Ks[row * KS_STR + c] = *(const float4*)&g_kh[go];
            *(float4*)&Vs[row * VS_STR + c] = *(const float4*)&g_vh[go];
        }
        __syncthreads();

        bool active = !((kt == 2 * qt + 1) && (wid < 4));
        if (active) {
            // S = Q K^T for this warp's 16 rows x 64 cols
            float s[8][4];
#pragma unroll
            for (int nt = 0; nt < 8; nt++)
#pragma unroll
                for (int j = 0; j < 4; j++) s[nt][j] = 0.f;
#pragma unroll
            for (int ks = 0; ks < 8; ks++) {
                unsigned a[4];
                int cb = ks * 8 + qd;
                a[0] = fu(Qs[(rb + g) * QS_STR + cb]);
                a[1] = fu(Qs[(rb + 8 + g) * QS_STR + cb]);
                a[2] = fu(Qs[(rb + g) * QS_STR + cb + 4]);
                a[3] = fu(Qs[(rb + 8 + g) * QS_STR + cb + 4]);
#pragma unroll
                for (int nt = 0; nt < 8; nt++) {
                    unsigned bb[2];
                    bb[0] = fu(Ks[(nt * 8 + g) * KS_STR + cb]);
                    bb[1] = fu(Ks[(nt * 8 + g) * KS_STR + cb + 4]);
                    mma8(s[nt], a, bb);
                }
            }

            // causal mask on diagonal tiles
            if (kt >= 2 * qt) {
#pragma unroll
                for (int nt = 0; nt < 8; nt++)
#pragma unroll
                    for (int j = 0; j < 4; j++) {
                        int col = kt * 64 + nt * 8 + 2 * qd + (j & 1);
                        int row = q0 + rb + g + (j >> 1) * 8;
                        if (col > row) s[nt][j] = -1e30f;
                    }
            }

            // online softmax, rows g (half 0) and g+8 (half 1)
#pragma unroll
            for (int half = 0; half < 2; half++) {
                int jo = half * 2;
                float mx = -1e30f;
#pragma unroll
                for (int nt = 0; nt < 8; nt++)
                    mx = fmaxf(mx, fmaxf(s[nt][jo], s[nt][jo + 1]));
                mx = fmaxf(mx, __shfl_xor_sync(0xffffffffu, mx, 1));
                mx = fmaxf(mx, __shfl_xor_sync(0xffffffffu, mx, 2));
                float mn = fmaxf(m2[half], mx);
                float corr = __expf(m2[half] - mn);
                float sum = 0.f;
                int prow = (rb + g + half * 8) * PS_STR;
#pragma unroll
                for (int nt = 0; nt < 8; nt++) {
                    float e0 = __expf(s[nt][jo] - mn);
                    float e1 = __expf(s[nt][jo + 1] - mn);
                    sum += e0 + e1;
                    Ps[prow + nt * 8 + 2 * qd] = to_tf32(e0);
                    Ps[prow + nt * 8 + 2 * qd + 1] = to_tf32(e1);
                }
                sum += __shfl_xor_sync(0xffffffffu, sum, 1);
                sum += __shfl_xor_sync(0xffffffffu, sum, 2);
                l2[half] = l2[half] * corr + sum;
                m2[half] = mn;
#pragma unroll
                for (int nt = 0; nt < 8; nt++) {
                    o[nt][jo] *= corr;
                    o[nt][jo + 1] *= corr;
                }
            }
            __syncwarp();

            // O += P V
#pragma unroll
            for (int ks = 0; ks < 8; ks++) {
                unsigned a[4];
                int cb = ks * 8 + qd;
                a[0] = fu(Ps[(rb + g) * PS_STR + cb]);
                a[1] = fu(Ps[(rb + 8 + g) * PS_STR + cb]);
                a[2] = fu(Ps[(rb + g) * PS_STR + cb + 4]);
                a[3] = fu(Ps[(rb + 8 + g) * PS_STR + cb + 4]);
#pragma unroll
                for (int nt = 0; nt < 8; nt++) {
                    unsigned bb[2];
                    bb[0] = fu(Vs[cb * VS_STR + nt * 8 + g]);
                    bb[1] = fu(Vs[(cb + 4) * VS_STR + nt * 8 + g]);
                    mma8(o[nt], a, bb);
                }
            }
        }
        __syncthreads();
    }

    // write out, layout (b, s, h, d)
#pragma unroll
    for (int half = 0; half < 2; half++) {
        int jo = half * 2;
        float inv = 1.f / l2[half];
        int row = q0 + rb + g + half * 8;
        size_t ob = (((size_t)b * NS + row) * NH + h) * DKH;
#pragma unroll
        for (int nt = 0; nt < 8; nt++) {
            int col = nt * 8 + 2 * qd;
            *(float2*)&g_att[ob + col] =
                make_float2(o[nt][jo] * inv, o[nt][jo + 1] * inv);
        }
    }
}

// ---------------------------------------------------------------------------
extern "C" void kernel_launch(void* const* d_in, const int* in_sizes, int n_in,
                              void* d_out, int out_size) {
    (void)in_sizes; (void)n_in; (void)out_size;
    const float* q = (const float*)d_in[0];
    const float* k = (const float*)d_in[1];
    const float* v = (const float*)d_in[2];
    // d_in[3] = mask (causal, known statically)
    const float* W_Aq = (const float*)d_in[4];
    const float* W_Ak = (const float*)d_in[5];
    const float* W_Av = (const float*)d_in[6];
    const float* W_Bq = (const float*)d_in[7];
    const float* W_Bk = (const float*)d_in[8];
    const float* W_Bv = (const float*)d_in[9];
    const float* Wo = (const float*)d_in[10];

    float* pAtt;
    cudaGetSymbolAddress((void**)&pAtt, g_att);

    // all 6 skinny projections, one launch
    proj_k<<<dim3(14, 32), 256>>>(q, k, v, W_Aq, W_Bq, W_Ak, W_Bk, W_Av, W_Bv);

    // rope + rank contraction (+ tf32 rounding)
    mix_k<<<NT, 128>>>();

    // causal flash attention
    cudaFuncSetAttribute(attn_k, cudaFuncAttributeMaxDynamicSharedMemorySize,
                         ATT_SMEM);
    attn_k<<<dim3(NS / 128, NH, NB), 256, ATT_SMEM>>>();

    // output projection -> d_out
    gemm_k<<<dim3(ND / 64, NT / 64 / 2), 256>>>(pAtt, Wo, (float*)d_out, ND, ND);
}

// round 3
// speedup vs baseline: 3.1836x; 1.4748x over previous
#include <cuda_runtime.h>

// ---------------------------------------------------------------------------
// T6 Tensor-Product Attention — tf32 mma.sync everywhere, fp32 accumulate.
// B=2, S=2048, D=1024, H=16, DK=64, Q_RANK=6, RANK=2, causal.
// ---------------------------------------------------------------------------

#define NB 2
#define NS 2048
#define ND 1024
#define NH 16
#define DKH 64
#define QR 6
#define RK 2
#define NT (NB * NS)  // 4096 tokens

// Scratch (device globals; allocation is forbidden)
__device__ float g_Aq[NT * 96];
__device__ float g_Bq[NT * 384];
__device__ float g_Ak[NT * 32];
__device__ float g_Bk[NT * 128];
__device__ float g_Av[NT * 32];
__device__ float g_Bv[NT * 128];
__device__ float g_qh[(size_t)NB * NH * NS * DKH];  // (b,h,s,d), tf32-rounded
__device__ float g_kh[(size_t)NB * NH * NS * DKH];
__device__ float g_vh[(size_t)NB * NH * NS * DKH];
__device__ float g_att[(size_t)NT * ND];            // (b,s,h*dk)

__device__ __forceinline__ float to_tf32(float x) {
    asm("cvt.rna.tf32.f32 %0, %0;" : "+f"(x));
    return x;
}
__device__ __forceinline__ unsigned fu(float x) { return __float_as_uint(x); }

// C[16x8] += A[16x8] * B[8x8], tf32 inputs, fp32 accum
__device__ __forceinline__ void mma8(float* c, const unsigned* a, const unsigned* b) {
    asm("mma.sync.aligned.m16n8k8.row.col.f32.tf32.tf32.f32 "
        "{%0,%1,%2,%3},{%4,%5,%6,%7},{%8,%9},{%0,%1,%2,%3};"
        : "+f"(c[0]), "+f"(c[1]), "+f"(c[2]), "+f"(c[3])
        : "r"(a[0]), "r"(a[1]), "r"(a[2]), "r"(a[3]), "r"(b[0]), "r"(b[1]));
}

// ---------------------------------------------------------------------------
// Generic tf32 GEMM body: C[m0:+128, n0:+64] = X[M,K] * W[K,N] tile.
// 256 threads = 8 warps (4 m x 2 n), warp tile 32x32, BK=32.
// Xs stride 36 (== 4 mod 32: conflict-free A-frag LDS);
// Ws stride 72 (== 8 mod 32: conflict-free B-frag LDS).
// Requires K % 32 == 0, N % 32 == 0, rows m0..m0+127 valid.
// ---------------------------------------------------------------------------
#define XS_STR 36
#define WS_STR 72

__device__ __forceinline__ void gemm_body(const float* __restrict__ X,
                                          const float* __restrict__ W,
                                          float* __restrict__ C, int N, int K,
                                          int m0, int n0, float* Xs, float* Ws) {
    const int tid = threadIdx.x;
    const int lane = tid & 31, wid = tid >> 5;
    const int g = lane >> 2, qd = lane & 3;
    const int wm = (wid & 3) * 32, wn = (wid >> 2) * 32;

    float acc[2][4][4];
#pragma unroll
    for (int mt = 0; mt < 2; mt++)
#pragma unroll
        for (int nt = 0; nt < 4; nt++)
#pragma unroll
            for (int j = 0; j < 4; j++) acc[mt][nt][j] = 0.f;

    for (int k0 = 0; k0 < K; k0 += 32) {
#pragma unroll
        for (int i = 0; i < 4; i++) {  // X tile 128x32 = 1024 float4
            int idx = tid + i * 256;
            int row = idx >> 3, c = (idx & 7) * 4;
            float4 vx = *(const float4*)&X[(size_t)(m0 + row) * K + k0 + c];
            vx.x = to_tf32(vx.x); vx.y = to_tf32(vx.y);
            vx.z = to_tf32(vx.z); vx.w = to_tf32(vx.w);
            *(float4*)&Xs[row * XS_STR + c] = vx;
        }
#pragma unroll
        for (int i = 0; i < 2; i++) {  // W tile 32x64 = 512 float4
            int idx = tid + i * 256;
            int r = idx >> 4, c = (idx & 15) * 4;
            int gn = n0 + c;
            float4 vw = make_float4(0.f, 0.f, 0.f, 0.f);
            if (gn < N) vw = *(const float4*)&W[(size_t)(k0 + r) * N + gn];
            vw.x = to_tf32(vw.x); vw.y = to_tf32(vw.y);
            vw.z = to_tf32(vw.z); vw.w = to_tf32(vw.w);
            *(float4*)&Ws[r * WS_STR + c] = vw;
        }
        __syncthreads();
#pragma unroll
        for (int ks = 0; ks < 4; ks++) {
            unsigned a[2][4], b[4][2];
#pragma unroll
            for (int mt = 0; mt < 2; mt++) {
                int rb = wm + mt * 16;
                int cb = ks * 8 + qd;
                a[mt][0] = fu(Xs[(rb + g) * XS_STR + cb]);
                a[mt][1] = fu(Xs[(rb + 8 + g) * XS_STR + cb]);
                a[mt][2] = fu(Xs[(rb + g) * XS_STR + cb + 4]);
                a[mt][3] = fu(Xs[(rb + 8 + g) * XS_STR + cb + 4]);
            }
#pragma unroll
            for (int nt = 0; nt < 4; nt++) {
                int nn = wn + nt * 8 + g;
                b[nt][0] = fu(Ws[(ks * 8 + qd) * WS_STR + nn]);
                b[nt][1] = fu(Ws[(ks * 8 + qd + 4) * WS_STR + nn]);
            }
#pragma unroll
            for (int mt = 0; mt < 2; mt++)
#pragma unroll
                for (int nt = 0; nt < 4; nt++) mma8(acc[mt][nt], a[mt], b[nt]);
        }
        __syncthreads();
    }

#pragma unroll
    for (int mt = 0; mt < 2; mt++)
#pragma unroll
        for (int nt = 0; nt < 4; nt++) {
            int row = m0 + wm + mt * 16 + g;
            int col = n0 + wn + nt * 8 + 2 * qd;
            if (col < N) {
                *(float2*)&C[(size_t)row * N + col] =
                    make_float2(acc[mt][nt][0], acc[mt][nt][1]);
                *(float2*)&C[(size_t)(row + 8) * N + col] =
                    make_float2(acc[mt][nt][2], acc[mt][nt][3]);
            }
        }
}

// Standalone GEMM (used for the Wo projection)
__global__ __launch_bounds__(256) void gemm_k(const float* __restrict__ X,
                                              const float* __restrict__ W,
                                              float* __restrict__ C, int N, int K) {
    __shared__ float Xs[128 * XS_STR];
    __shared__ float Ws[32 * WS_STR];
    gemm_body(X, W, C, N, K, blockIdx.y * 128, blockIdx.x * 64, Xs, Ws);
}

// All 6 skinny projections in one launch. grid = (14 col-slots, 32 row-tiles).
__global__ __launch_bounds__(256) void proj_k(const float* __restrict__ q,
                                              const float* __restrict__ k,
                                              const float* __restrict__ v,
                                              const float* __restrict__ WAq,
                                              const float* __restrict__ WBq,
                                              const float* __restrict__ WAk,
                                              const float* __restrict__ WBk,
                                              const float* __restrict__ WAv,
                                              const float* __restrict__ WBv) {
    __shared__ float Xs[128 * XS_STR];
    __shared__ float Ws[32 * WS_STR];
    const int slot = blockIdx.x;
    const int slot_seg[14] = {0, 0, 1, 1, 1, 1, 1, 1, 2, 3, 3, 4, 5, 5};
    const int slot_n0[14] = {0, 64, 0, 64, 128, 192, 256, 320, 0, 0, 64, 0, 0, 64};
    const int seg = slot_seg[slot];
    const int seg_N[6] = {96, 384, 32, 128, 32, 128};
    const float* Xp = (seg < 2) ? q : (seg < 4) ? k : v;
    const float* Wp;
    float* Cp;
    switch (seg) {
        case 0: Wp = WAq; Cp = g_Aq; break;
        case 1: Wp = WBq; Cp = g_Bq; break;
        case 2: Wp = WAk; Cp = g_Ak; break;
        case 3: Wp = WBk; Cp = g_Bk; break;
        case 4: Wp = WAv; Cp = g_Av; break;
        default: Wp = WBv; Cp = g_Bv; break;
    }
    gemm_body(Xp, Wp, Cp, seg_N[seg], ND, blockIdx.y * 128, slot_n0[slot], Xs, Ws);
}

// ---------------------------------------------------------------------------
// RoPE + rank contraction -> qh/kh/vh (b,h,s,d), tf32-rounded.
// Folds 1/(Q_RANK*DK) into qh and 1/RANK into kh, vh.
// ---------------------------------------------------------------------------
__global__ __launch_bounds__(128) void mix_k() {
    const int t = blockIdx.x;
    const int b = t >> 11;
    const int s = t & (NS - 1);
    const int tid = threadIdx.x;

    __shared__ float sAq[96], sAk[32], sAv[32];
    __shared__ float sBq[384], sBk[128], sBv[128];

    if (tid < 96) sAq[tid] = g_Aq[t * 96 + tid];
    if (tid < 32) {
        sAk[tid] = g_Ak[t * 32 + tid];
        sAv[tid] = g_Av[t * 32 + tid];
    }
    for (int i = tid; i < 384; i += 128) sBq[i] = g_Bq[t * 384 + i];
    sBk[tid] = g_Bk[t * 128 + tid];
    sBv[tid] = g_Bv[t * 128 + tid];
    __syncthreads();

    for (int i = tid; i < (QR + RK) * 32; i += 128) {
        int r = i >> 5;
        int dd = i & 31;
        float inv = (float)pow(10000.0, -(double)dd / 32.0);
        float ang = (float)s * inv;
        float c, sn;
        sincosf(ang, &sn, &c);
        float* base = (r < QR) ? &sBq[r * DKH] : &sBk[(r - QR) * DKH];
        float x1 = base[dd];
        float x2 = base[dd + 32];
        base[dd] = x1 * c + x2 * sn;
        base[dd + 32] = -x1 * sn + x2 * c;
    }
    __syncthreads();

    const float qsc = 1.f / (6.f * 64.f);
    for (int i = tid; i < NH * DKH; i += 128) {
        int h = i >> 6;
        int d = i & 63;
        float aq = 0.f;
#pragma unroll
        for (int r = 0; r < QR; r++) aq += sAq[h * QR + r] * sBq[r * DKH + d];
        size_t o = (((size_t)b * NH + h) * NS + s) * DKH + d;
        g_qh[o] = to_tf32(aq * qsc);
        float ak = sAk[h * RK + 0] * sBk[d] + sAk[h * RK + 1] * sBk[DKH + d];
        g_kh[o] = to_tf32(ak * 0.5f);
        float av = sAv[h * RK + 0] * sBv[d] + sAv[h * RK + 1] * sBv[DKH + d];
        g_vh[o] = to_tf32(av * 0.5f);
    }
}

// ---------------------------------------------------------------------------
// Causal flash attention, tf32 mma. Q tile 128, KV tile 64.
// 8 warps, each warp: 16 q rows x 64 kv cols (m16 x 8 n-tiles, k in 8-steps).
// Smem strides: A-pattern arrays (Qs, Ks, Ps) 68 (==4 mod 32);
//               B-pattern with k in row dim (Vs) 72 (==8 mod 32).
// ---------------------------------------------------------------------------
#define QS_STR 68
#define KS_STR 68
#define VS_STR 72
#define PS_STR 68
#define ATT_SMEM ((128 * QS_STR + 64 * KS_STR + 64 * VS_STR + 128 * PS_STR) * 4)

__global__ __launch_bounds__(256) void attn_k() {
    extern __shared__ float sm[];
    float* Qs = sm;                     // [q][d]   128 x 68
    float* Ks = Qs + 128 * QS_STR;      // [key][d]  64 x 68
    float* Vs = Ks + 64 * KS_STR;       // [key][d]  64 x 72
    float* Ps = Vs + 64 * VS_STR;       // [q][key] 128 x 68

    const int qt = blockIdx.x, h = blockIdx.y, b = blockIdx.z;
    const int q0 = qt * 128;
    const int tid = threadIdx.x, lane = tid & 31, wid = tid >> 5;
    const int g = lane >> 2, qd = lane & 3;
    const size_t bh = ((size_t)b * NH + h) * NS * DKH;
    const int rb = wid * 16;  // warp's q-row base within the tile

#pragma unroll
    for (int i = 0; i < 8; i++) {  // Q tile 128x64 = 2048 float4
        int idx = tid + i * 256;
        int row = idx >> 4, c = (idx & 15) * 4;
        *(float4*)&Qs[row * QS_STR + c] =
            *(const float4*)&g_qh[bh + (size_t)(q0 + row) * DKH + c];
    }

    float m2[2] = {-1e30f, -1e30f};
    float l2[2] = {0.f, 0.f};
    float o[8][4];
#pragma unroll
    for (int nt = 0; nt < 8; nt++)
#pragma unroll
        for (int j = 0; j < 4; j++) o[nt][j] = 0.f;

    __syncthreads();

    const int nkt = 2 * qt + 2;
    for (int kt = 0; kt < nkt; kt++) {
#pragma unroll
        for (int i = 0; i < 4; i++) {  // K,V tiles 64x64 each
            int idx = tid + i * 256;
            int row = idx >> 4, c = (idx & 15) * 4;
            size_t go = bh + (size_t)(kt * 64 + row) * DKH + c;
            *(float4*)&Ks[row * KS_STR + c] = *(const float4*)&g_kh[go];
            *(float4*)&Vs[row * VS_STR + c] = *(const float4*)&g_vh[go];
        }
        __syncthreads();

        bool active = !((kt == 2 * qt + 1) && (wid < 4));
        if (active) {
            // S = Q K^T for this warp's 16 rows x 64 cols
            float s[8][4];
#pragma unroll
            for (int nt = 0; nt < 8; nt++)
#pragma unroll
                for (int j = 0; j < 4; j++) s[nt][j] = 0.f;
#pragma unroll
            for (int ks = 0; ks < 8; ks++) {
                unsigned a[4];
                int cb = ks * 8 + qd;
                a[0] = fu(Qs[(rb + g) * QS_STR + cb]);
                a[1] = fu(Qs[(rb + 8 + g) * QS_STR + cb]);
                a[2] = fu(Qs[(rb + g) * QS_STR + cb + 4]);
                a[3] = fu(Qs[(rb + 8 + g) * QS_STR + cb + 4]);
#pragma unroll
                for (int nt = 0; nt < 8; nt++) {
                    unsigned bb[2];
                    bb[0] = fu(Ks[(nt * 8 + g) * KS_STR + cb]);
                    bb[1] = fu(Ks[(nt * 8 + g) * KS_STR + cb + 4]);
                    mma8(s[nt], a, bb);
                }
            }

            // causal mask on diagonal tiles
            if (kt >= 2 * qt) {
#pragma unroll
                for (int nt = 0; nt < 8; nt++)
#pragma unroll
                    for (int j = 0; j < 4; j++) {
                        int col = kt * 64 + nt * 8 + 2 * qd + (j & 1);
                        int row = q0 + rb + g + (j >> 1) * 8;
                        if (col > row) s[nt][j] = -1e30f;
                    }
            }

            // online softmax, rows g (half 0) and g+8 (half 1)
#pragma unroll
            for (int half = 0; half < 2; half++) {
                int jo = half * 2;
                float mx = -1e30f;
#pragma unroll
                for (int nt = 0; nt < 8; nt++)
                    mx = fmaxf(mx, fmaxf(s[nt][jo], s[nt][jo + 1]));
                mx = fmaxf(mx, __shfl_xor_sync(0xffffffffu, mx, 1));
                mx = fmaxf(mx, __shfl_xor_sync(0xffffffffu, mx, 2));
                float mn = fmaxf(m2[half], mx);
                float corr = __expf(m2[half] - mn);
                float sum = 0.f;
                int prow = (rb + g + half * 8) * PS_STR;
#pragma unroll
                for (int nt = 0; nt < 8; nt++) {
                    float e0 = __expf(s[nt][jo] - mn);
                    float e1 = __expf(s[nt][jo + 1] - mn);
                    sum += e0 + e1;
                    Ps[prow + nt * 8 + 2 * qd] = to_tf32(e0);
                    Ps[prow + nt * 8 + 2 * qd + 1] = to_tf32(e1);
                }
                sum += __shfl_xor_sync(0xffffffffu, sum, 1);
                sum += __shfl_xor_sync(0xffffffffu, sum, 2);
                l2[half] = l2[half] * corr + sum;
                m2[half] = mn;
#pragma unroll
                for (int nt = 0; nt < 8; nt++) {
                    o[nt][jo] *= corr;
                    o[nt][jo + 1] *= corr;
                }
            }
            __syncwarp();

            // O += P V
#pragma unroll
            for (int ks = 0; ks < 8; ks++) {
                unsigned a[4];
                int cb = ks * 8 + qd;
                a[0] = fu(Ps[(rb + g) * PS_STR + cb]);
                a[1] = fu(Ps[(rb + 8 + g) * PS_STR + cb]);
                a[2] = fu(Ps[(rb + g) * PS_STR + cb + 4]);
                a[3] = fu(Ps[(rb + 8 + g) * PS_STR + cb + 4]);
#pragma unroll
                for (int nt = 0; nt < 8; nt++) {
                    unsigned bb[2];
                    bb[0] = fu(Vs[cb * VS_STR + nt * 8 + g]);
                    bb[1] = fu(Vs[(cb + 4) * VS_STR + nt * 8 + g]);
                    mma8(o[nt], a, bb);
                }
            }
        }
        __syncthreads();
    }

    // write out, layout (b, s, h, d)
#pragma unroll
    for (int half = 0; half < 2; half++) {
        int jo = half * 2;
        float inv = 1.f / l2[half];
        int row = q0 + rb + g + half * 8;
        size_t ob = (((size_t)b * NS + row) * NH + h) * DKH;
#pragma unroll
        for (int nt = 0; nt < 8; nt++) {
            int col = nt * 8 + 2 * qd;
            *(float2*)&g_att[ob + col] =
                make_float2(o[nt][jo] * inv, o[nt][jo + 1] * inv);
        }
    }
}

// ---------------------------------------------------------------------------
extern "C" void kernel_launch(void* const* d_in, const int* in_sizes, int n_in,
                              void* d_out, int out_size) {
    (void)in_sizes; (void)n_in; (void)out_size;
    const float* q = (const float*)d_in[0];
    const float* k = (const float*)d_in[1];
    const float* v = (const float*)d_in[2];
    // d_in[3] = mask (causal, known statically)
    const float* W_Aq = (const float*)d_in[4];
    const float* W_Ak = (const float*)d_in[5];
    const float* W_Av = (const float*)d_in[6];
    const float* W_Bq = (const float*)d_in[7];
    const float* W_Bk = (const float*)d_in[8];
    const float* W_Bv = (const float*)d_in[9];
    const float* Wo = (const float*)d_in[10];

    float* pAtt;
    cudaGetSymbolAddress((void**)&pAtt, g_att);

    // all 6 skinny projections, one launch
    proj_k<<<dim3(14, 32), 256>>>(q, k, v, W_Aq, W_Bq, W_Ak, W_Bk, W_Av, W_Bv);

    // rope + rank contraction (+ tf32 rounding)
    mix_k<<<NT, 128>>>();

    // causal flash attention
    cudaFuncSetAttribute(attn_k, cudaFuncAttributeMaxDynamicSharedMemorySize,
                         ATT_SMEM);
    attn_k<<<dim3(NS / 128, NH, NB), 256, ATT_SMEM>>>();

    // output projection -> d_out
    gemm_k<<<dim3(ND / 64, NT / 64 / 2), 256>>>(pAtt, Wo, (float*)d_out, ND, ND);
}

// round 4
// speedup vs baseline: 3.5241x; 1.1069x over previous
#include <cuda_runtime.h>

#define NB 2
#define NS 2048
#define ND 1024
#define NH 16
#define DKH 64
#define QR 6
#define RK 2
#define NT (NB * NS)

__device__ float g_Aq[NT * 96];
__device__ float g_Bq[NT * 384];
__device__ float g_Ak[NT * 32];
__device__ float g_Bk[NT * 128];
__device__ float g_Av[NT * 32];
__device__ float g_Bv[NT * 128];
__device__ float g_qh[(size_t)NB * NH * NS * DKH];
__device__ float g_kh[(size_t)NB * NH * NS * DKH];
__device__ float g_vh[(size_t)NB * NH * NS * DKH];
__device__ float g_att[(size_t)NT * ND];

__device__ __forceinline__ float to_tf32(float x) {
    asm("cvt.rna.tf32.f32 %0, %0;" : "+f"(x));
    return x;
}
__device__ __forceinline__ unsigned fu(float x) { return __float_as_uint(x); }

__device__ __forceinline__ void mma8(float* c, const unsigned* a, const unsigned* b) {
    asm("mma.sync.aligned.m16n8k8.row.col.f32.tf32.tf32.f32 "
        "{%0,%1,%2,%3},{%4,%5,%6,%7},{%8,%9},{%0,%1,%2,%3};"
        : "+f"(c[0]), "+f"(c[1]), "+f"(c[2]), "+f"(c[3])
        : "r"(a[0]), "r"(a[1]), "r"(a[2]), "r"(a[3]), "r"(b[0]), "r"(b[1]));
}

__device__ __forceinline__ void ldsm4(unsigned* r, const float* p) {
    unsigned a = (unsigned)__cvta_generic_to_shared(p);
    asm volatile("ldmatrix.sync.aligned.m8n8.x4.shared.b16 {%0,%1,%2,%3},[%4];"
                 : "=r"(r[0]), "=r"(r[1]), "=r"(r[2]), "=r"(r[3]) : "r"(a));
}

// ---------------------------------------------------------------------------
// tf32 GEMM: C[m0:+128, n0:+128] = X[M,K]*W[K,N]. 8 warps (2m x 4n),
// warp tile 64x32, BK=16, ldmatrix A-frags, register prefetch.
// ---------------------------------------------------------------------------
#define GXS 20
#define GWS 136

__device__ __forceinline__ void gemm3(const float* __restrict__ X,
                                      const float* __restrict__ W,
                                      float* __restrict__ C, int N, int K,
                                      int m0, int n0) {
    __shared__ float Xs[128 * GXS];
    __shared__ float Ws[16 * GWS];
    const int tid = threadIdx.x, lane = tid & 31, wid = tid >> 5;
    const int g = lane >> 2, qd = lane & 3;
    const int wm = (wid & 1) * 64, wn = (wid >> 1) * 32;
    const int ar = (lane & 7) + ((lane >> 3) & 1) * 8, ac = (lane >> 4) * 4;

    const int fm = tid >> 1, fh = (tid & 1) * 8;
    const int fk = tid >> 5, fn = (tid & 31) * 4;
    const bool wok = (n0 + fn) < N;
    const float* Xr = X + (size_t)(m0 + fm) * K + fh;
    const float* Wr = W + (size_t)fk * N + n0 + fn;

    float acc[4][4][4];
#pragma unroll
    for (int mt = 0; mt < 4; mt++)
#pragma unroll
        for (int nt = 0; nt < 4; nt++)
#pragma unroll
            for (int j = 0; j < 4; j++) acc[mt][nt][j] = 0.f;

    const float4 z4 = make_float4(0.f, 0.f, 0.f, 0.f);
    float4 xa0 = *(const float4*)&Xr[0];
    float4 xa1 = *(const float4*)&Xr[4];
    float4 wa0 = wok ? *(const float4*)&Wr[0] : z4;
    float4 wa1 = wok ? *(const float4*)&Wr[(size_t)8 * N] : z4;

    for (int k0 = 0; k0 < K; k0 += 16) {
        *(float4*)&Xs[fm * GXS + fh] =
            make_float4(to_tf32(xa0.x), to_tf32(xa0.y), to_tf32(xa0.z), to_tf32(xa0.w));
        *(float4*)&Xs[fm * GXS + fh + 4] =
            make_float4(to_tf32(xa1.x), to_tf32(xa1.y), to_tf32(xa1.z), to_tf32(xa1.w));
        *(float4*)&Ws[fk * GWS + fn] =
            make_float4(to_tf32(wa0.x), to_tf32(wa0.y), to_tf32(wa0.z), to_tf32(wa0.w));
        *(float4*)&Ws[(fk + 8) * GWS + fn] =
            make_float4(to_tf32(wa1.x), to_tf32(wa1.y), to_tf32(wa1.z), to_tf32(wa1.w));
        __syncthreads();
        if (k0 + 16 < K) {
            xa0 = *(const float4*)&Xr[k0 + 16];
            xa1 = *(const float4*)&Xr[k0 + 20];
            wa0 = wok ? *(const float4*)&Wr[(size_t)(k0 + 16) * N] : z4;
            wa1 = wok ? *(const float4*)&Wr[(size_t)(k0 + 24) * N] : z4;
        }
#pragma unroll
        for (int ks = 0; ks < 2; ks++) {
            unsigned a[4][4];
#pragma unroll
            for (int mt = 0; mt < 4; mt++)
                ldsm4(a[mt], &Xs[(wm + mt * 16 + ar) * GXS + ks * 8 + ac]);
#pragma unroll
            for (int nt = 0; nt < 4; nt++) {
                unsigned bb[2];
                bb[0] = fu(Ws[(ks * 8 + qd) * GWS + wn + nt * 8 + g]);
                bb[1] = fu(Ws[(ks * 8 + qd + 4) * GWS + wn + nt * 8 + g]);
#pragma unroll
                for (int mt = 0; mt < 4; mt++) mma8(acc[mt][nt], a[mt], bb);
            }
        }
        __syncthreads();
    }

#pragma unroll
    for (int mt = 0; mt < 4; mt++)
#pragma unroll
        for (int nt = 0; nt < 4; nt++) {
            int row = m0 + wm + mt * 16 + g;
            int col = n0 + wn + nt * 8 + 2 * qd;
            if (col < N) {
                *(float2*)&C[(size_t)row * N + col] =
                    make_float2(acc[mt][nt][0], acc[mt][nt][1]);
                *(float2*)&C[(size_t)(row + 8) * N + col] =
                    make_float2(acc[mt][nt][2], acc[mt][nt][3]);
            }
        }
}

__global__ __launch_bounds__(256, 2) void gemm_k(const float* __restrict__ X,
                                                 const float* __restrict__ W,
                                                 float* __restrict__ C, int N,
                                                 int K) {
    gemm3(X, W, C, N, K, blockIdx.y * 128, blockIdx.x * 128);
}

__global__ __launch_bounds__(256, 2) void proj_k(
    const float* __restrict__ q, const float* __restrict__ k,
    const float* __restrict__ v, const float* __restrict__ WAq,
    const float* __restrict__ WBq, const float* __restrict__ WAk,
    const float* __restrict__ WBk, const float* __restrict__ WAv,
    const float* __restrict__ WBv) {
    const int slot = blockIdx.x;
    const int slot_seg[8] = {0, 1, 1, 1, 2, 3, 4, 5};
    const int slot_n0[8] = {0, 0, 128, 256, 0, 0, 0, 0};
    const int seg = slot_seg[slot];
    const int seg_N[6] = {96, 384, 32, 128, 32, 128};
    const float* Xp = (seg < 2) ? q : (seg < 4) ? k : v;
    const float* Wp;
    float* Cp;
    switch (seg) {
        case 0: Wp = WAq; Cp = g_Aq; break;
        case 1: Wp = WBq; Cp = g_Bq; break;
        case 2: Wp = WAk; Cp = g_Ak; break;
        case 3: Wp = WBk; Cp = g_Bk; break;
        case 4: Wp = WAv; Cp = g_Av; break;
        default: Wp = WBv; Cp = g_Bv; break;
    }
    gemm3(Xp, Wp, Cp, seg_N[seg], ND, blockIdx.y * 128, slot_n0[slot]);
}

// ---------------------------------------------------------------------------
// RoPE + rank contraction -> qh/kh/vh (b,h,s,d), tf32-rounded.
// ---------------------------------------------------------------------------
__global__ __launch_bounds__(128) void mix_k() {
    const int t = blockIdx.x;
    const int b = t >> 11;
    const int s = t & (NS - 1);
    const int tid = threadIdx.x;

    __shared__ float sAq[96], sAk[32], sAv[32];
    __shared__ float sBq[384], sBk[128], sBv[128];

    if (tid < 96) sAq[tid] = g_Aq[t * 96 + tid];
    if (tid < 32) {
        sAk[tid] = g_Ak[t * 32 + tid];
        sAv[tid] = g_Av[t * 32 + tid];
    }
    for (int i = tid; i < 384; i += 128) sBq[i] = g_Bq[t * 384 + i];
    sBk[tid] = g_Bk[t * 128 + tid];
    sBv[tid] = g_Bv[t * 128 + tid];
    __syncthreads();

    for (int i = tid; i < (QR + RK) * 32; i += 128) {
        int r = i >> 5, dd = i & 31;
        float inv = (float)pow(10000.0, -(double)dd / 32.0);
        float c, sn;
        sincosf((float)s * inv, &sn, &c);
        float* base = (r < QR) ? &sBq[r * DKH] : &sBk[(r - QR) * DKH];
        float x1 = base[dd], x2 = base[dd + 32];
        base[dd] = x1 * c + x2 * sn;
        base[dd + 32] = -x1 * sn + x2 * c;
    }
    __syncthreads();

    const float qsc = 1.f / (6.f * 64.f);
    for (int i = tid; i < NH * DKH; i += 128) {
        int h = i >> 6, d = i & 63;
        float aq = 0.f;
#pragma unroll
        for (int r = 0; r < QR; r++) aq += sAq[h * QR + r] * sBq[r * DKH + d];
        size_t o = (((size_t)b * NH + h) * NS + s) * DKH + d;
        g_qh[o] = to_tf32(aq * qsc);
        g_kh[o] = to_tf32((sAk[h * RK] * sBk[d] + sAk[h * RK + 1] * sBk[DKH + d]) * 0.5f);
        g_vh[o] = to_tf32((sAv[h * RK] * sBv[d] + sAv[h * RK + 1] * sBv[DKH + d]) * 0.5f);
    }
}

// ---------------------------------------------------------------------------
// Causal flash attention: Q tile 128, KV tile 64, 8 warps (16 q-rows each).
// Q A-frags + K B-frags via ldmatrix.x4; P C-frag -> A-frag via shuffles.
// ---------------------------------------------------------------------------
#define QS_STR 68
#define KS_STR 68
#define VS_STR 72
#define ATT_SMEM ((128 * QS_STR + 64 * KS_STR + 64 * VS_STR) * 4)

__global__ __launch_bounds__(256) void attn_k() {
    extern __shared__ float sm[];
    float* Qs = sm;                 // [q][d]
    float* Ks = Qs + 128 * QS_STR;  // [key][d]
    float* Vs = Ks + 64 * KS_STR;   // [key][d]

    const int qt = gridDim.x - 1 - blockIdx.x;  // heavy tiles first
    const int h = blockIdx.y, b = blockIdx.z;
    const int q0 = qt * 128;
    const int tid = threadIdx.x, lane = tid & 31, wid = tid >> 5;
    const int g = lane >> 2, qd = lane & 3;
    const size_t bh = ((size_t)b * NH + h) * NS * DKH;
    const int rb = wid * 16;
    const int ar = (lane & 7) + ((lane >> 3) & 1) * 8, ac = (lane >> 4) * 4;
    const int sl1 = (lane & 28) | (qd >> 1), sl2 = sl1 + 2;

#pragma unroll
    for (int i = 0; i < 8; i++) {
        int idx = tid + i * 256;
        int row = idx >> 4, c4 = (idx & 15) * 4;
        *(float4*)&Qs[row * QS_STR + c4] =
            *(const float4*)&g_qh[bh + (size_t)(q0 + row) * DKH + c4];
    }

    float m2[2] = {-1e30f, -1e30f};
    float l2[2] = {0.f, 0.f};
    float o[8][4];
#pragma unroll
    for (int nt = 0; nt < 8; nt++)
#pragma unroll
        for (int j = 0; j < 4; j++) o[nt][j] = 0.f;

    __syncthreads();

    const int nkt = 2 * qt + 2;
    for (int kt = 0; kt < nkt; kt++) {
#pragma unroll
        for (int i = 0; i < 4; i++) {
            int idx = tid + i * 256;
            int row = idx >> 4, c4 = (idx & 15) * 4;
            size_t go = bh + (size_t)(kt * 64 + row) * DKH + c4;
            *(float4*)&Ks[row * KS_STR + c4] = *(const float4*)&g_kh[go];
            *(float4*)&Vs[row * VS_STR + c4] = *(const float4*)&g_vh[go];
        }
        __syncthreads();

        if (!((kt == 2 * qt + 1) && (wid < 4))) {
            float s[8][4];
#pragma unroll
            for (int nt = 0; nt < 8; nt++)
#pragma unroll
                for (int j = 0; j < 4; j++) s[nt][j] = 0.f;
#pragma unroll
            for (int ks = 0; ks < 8; ks++) {
                unsigned a[4];
                ldsm4(a, &Qs[(rb + ar) * QS_STR + ks * 8 + ac]);
#pragma unroll
                for (int p = 0; p < 4; p++) {
                    unsigned kb[4];
                    ldsm4(kb, &Ks[(p * 16 + ar) * KS_STR + ks * 8 + ac]);
                    unsigned b0[2] = {kb[0], kb[2]}, b1[2] = {kb[1], kb[3]};
                    mma8(s[2 * p], a, b0);
                    mma8(s[2 * p + 1], a, b1);
                }
            }

            if (kt >= 2 * qt) {
#pragma unroll
                for (int nt = 0; nt < 8; nt++)
#pragma unroll
                    for (int j = 0; j < 4; j++) {
                        int col = kt * 64 + nt * 8 + 2 * qd + (j & 1);
                        int row = q0 + rb + g + (j >> 1) * 8;
                        if (col > row) s[nt][j] = -1e30f;
                    }
            }

#pragma unroll
            for (int half = 0; half < 2; half++) {
                int jo = half * 2;
                float mx = -1e30f;
#pragma unroll
                for (int nt = 0; nt < 8; nt++)
                    mx = fmaxf(mx, fmaxf(s[nt][jo], s[nt][jo + 1]));
                mx = fmaxf(mx, __shfl_xor_sync(0xffffffffu, mx, 1));
                mx = fmaxf(mx, __shfl_xor_sync(0xffffffffu, mx, 2));
                float mn = fmaxf(m2[half], mx);
                float corr = __expf(m2[half] - mn);
                float sum = 0.f;
#pragma unroll
                for (int nt = 0; nt < 8; nt++) {
                    float e0 = __expf(s[nt][jo] - mn);
                    float e1 = __expf(s[nt][jo + 1] - mn);
                    sum += e0 + e1;
                    s[nt][jo] = e0;
                    s[nt][jo + 1] = e1;
                }
                sum += __shfl_xor_sync(0xffffffffu, sum, 1);
                sum += __shfl_xor_sync(0xffffffffu, sum, 2);
                l2[half] = l2[half] * corr + sum;
                m2[half] = mn;
#pragma unroll
                for (int nt = 0; nt < 8; nt++) {
                    o[nt][jo] *= corr;
                    o[nt][jo + 1] *= corr;
                }
            }

            // P C-frag -> A-frag by shuffle, then O += P V
#pragma unroll
            for (int kc = 0; kc < 8; kc++) {
                float c0 = s[kc][0], c1 = s[kc][1], c2 = s[kc][2], c3 = s[kc][3];
                float u0a = __shfl_sync(0xffffffffu, c0, sl1);
                float u0b = __shfl_sync(0xffffffffu, c1, sl1);
                float u1a = __shfl_sync(0xffffffffu, c2, sl1);
                float u1b = __shfl_sync(0xffffffffu, c3, sl1);
                float u2a = __shfl_sync(0xffffffffu, c0, sl2);
                float u2b = __shfl_sync(0xffffffffu, c1, sl2);
                float u3a = __shfl_sync(0xffffffffu, c2, sl2);
                float u3b = __shfl_sync(0xffffffffu, c3, sl2);
                bool od = qd & 1;
                unsigned a[4];
                a[0] = fu(to_tf32(od ? u0b : u0a));
                a[1] = fu(to_tf32(od ? u1b : u1a));
                a[2] = fu(to_tf32(od ? u2b : u2a));
                a[3] = fu(to_tf32(od ? u3b : u3a));
                int cb = kc * 8;
#pragma unroll
                for (int nt = 0; nt < 8; nt++) {
                    unsigned bb[2];
                    bb[0] = fu(Vs[(cb + qd) * VS_STR + nt * 8 + g]);
                    bb[1] = fu(Vs[(cb + qd + 4) * VS_STR + nt * 8 + g]);
                    mma8(o[nt], a, bb);
                }
            }
        }
        __syncthreads();
    }

#pragma unroll
    for (int half = 0; half < 2; half++) {
        int jo = half * 2;
        float inv = 1.f / l2[half];
        int row = q0 + rb + g + half * 8;
        size_t ob = (((size_t)b * NS + row) * NH + h) * DKH;
#pragma unroll
        for (int nt = 0; nt < 8; nt++) {
            int col = nt * 8 + 2 * qd;
            *(float2*)&g_att[ob + col] =
                make_float2(o[nt][jo] * inv, o[nt][jo + 1] * inv);
        }
    }
}

// ---------------------------------------------------------------------------
extern "C" void kernel_launch(void* const* d_in, const int* in_sizes, int n_in,
                              void* d_out, int out_size) {
    (void)in_sizes; (void)n_in; (void)out_size;
    const float* q = (const float*)d_in[0];
    const float* k = (const float*)d_in[1];
    const float* v = (const float*)d_in[2];
    const float* W_Aq = (const float*)d_in[4];
    const float* W_Ak = (const float*)d_in[5];
    const float* W_Av = (const float*)d_in[6];
    const float* W_Bq = (const float*)d_in[7];
    const float* W_Bk = (const float*)d_in[8];
    const float* W_Bv = (const float*)d_in[9];
    const float* Wo = (const float*)d_in[10];

    float* pAtt;
    cudaGetSymbolAddress((void**)&pAtt, g_att);

    proj_k<<<dim3(8, 32), 256>>>(q, k, v, W_Aq, W_Bq, W_Ak, W_Bk, W_Av, W_Bv);
    mix_k<<<NT, 128>>>();
    cudaFuncSetAttribute(attn_k, cudaFuncAttributeMaxDynamicSharedMemorySize,
                         ATT_SMEM);
    attn_k<<<dim3(NS / 128, NH, NB), 256, ATT_SMEM>>>();
    gemm_k<<<dim3(ND / 128, NT / 128), 256>>>(pAtt, Wo, (float*)d_out, ND, ND);
}

// round 9
// speedup vs baseline: 3.6016x; 1.0220x over previous
#include <cuda_runtime.h>

#define NB 2
#define NS 2048
#define ND 1024
#define NH 16
#define DKH 64
#define QR 6
#define RK 2
#define NT (NB * NS)

__device__ float g_Aq[NT * 96];
__device__ float g_Bq[NT * 384];
__device__ float g_Ak[NT * 32];
__device__ float g_Bk[NT * 128];
__device__ float g_Av[NT * 32];
__device__ float g_Bv[NT * 128];
__device__ float g_qh[(size_t)NB * NH * NS * DKH];
__device__ float g_kh[(size_t)NB * NH * NS * DKH];
__device__ float g_vh[(size_t)NB * NH * NS * DKH];
__device__ float g_att[(size_t)NT * ND];

__device__ __forceinline__ float to_tf32(float x) {
    asm("cvt.rna.tf32.f32 %0, %0;" : "+f"(x));
    return x;
}
__device__ __forceinline__ unsigned fu(float x) { return __float_as_uint(x); }

__device__ __forceinline__ void mma8(float* c, const unsigned* a, const unsigned* b) {
    asm("mma.sync.aligned.m16n8k8.row.col.f32.tf32.tf32.f32 "
        "{%0,%1,%2,%3},{%4,%5,%6,%7},{%8,%9},{%0,%1,%2,%3};"
        : "+f"(c[0]), "+f"(c[1]), "+f"(c[2]), "+f"(c[3])
        : "r"(a[0]), "r"(a[1]), "r"(a[2]), "r"(a[3]), "r"(b[0]), "r"(b[1]));
}

__device__ __forceinline__ void ldsm4(unsigned* r, const float* p) {
    unsigned a = (unsigned)__cvta_generic_to_shared(p);
    asm volatile("ldmatrix.sync.aligned.m8n8.x4.shared.b16 {%0,%1,%2,%3},[%4];"
                 : "=r"(r[0]), "=r"(r[1]), "=r"(r[2]), "=r"(r[3]) : "r"(a));
}

__device__ __forceinline__ void cpa16(float* s, const float* g) {
    unsigned sa = (unsigned)__cvta_generic_to_shared(s);
    asm volatile("cp.async.cg.shared.global [%0],[%1],16;" ::"r"(sa), "l"(g));
}
#define CP_COMMIT() asm volatile("cp.async.commit_group;")
#define CP_WAIT0() asm volatile("cp.async.wait_group 0;" ::: "memory")

// ---------------------------------------------------------------------------
// tf32 GEMM: C[m0:+128, n0:+128] = X[M,K]*W[K,N]. 8 warps (2m x 4n),
// warp tile 64x32, BK=16, ldmatrix A-frags, double-buffered smem,
// one barrier per BK step. Static smem = 37.9KB (< 48KB static cap).
// ---------------------------------------------------------------------------
#define GXS 20
#define GWS 136

__device__ __forceinline__ void gemm3(const float* __restrict__ X,
                                      const float* __restrict__ W,
                                      float* __restrict__ C, int N, int K,
                                      int m0, int n0) {
    __shared__ float Xs[2][128 * GXS];
    __shared__ float Ws[2][16 * GWS];
    const int tid = threadIdx.x, lane = tid & 31, wid = tid >> 5;
    const int g = lane >> 2, qd = lane & 3;
    const int wm = (wid & 1) * 64, wn = (wid >> 1) * 32;
    const int ar = (lane & 7) + ((lane >> 3) & 1) * 8, ac = (lane >> 4) * 4;

    const int fm = tid >> 1, fh = (tid & 1) * 8;
    const int fk = tid >> 5, fn = (tid & 31) * 4;
    const bool wok = (n0 + fn) < N;
    const float* Xr = X + (size_t)(m0 + fm) * K + fh;
    const float* Wr = W + (size_t)fk * N + n0 + fn;

    float acc[4][4][4];
#pragma unroll
    for (int mt = 0; mt < 4; mt++)
#pragma unroll
        for (int nt = 0; nt < 4; nt++)
#pragma unroll
            for (int j = 0; j < 4; j++) acc[mt][nt][j] = 0.f;

    const float4 z4 = make_float4(0.f, 0.f, 0.f, 0.f);
    float4 xa0 = *(const float4*)&Xr[0];
    float4 xa1 = *(const float4*)&Xr[4];
    float4 wa0 = wok ? *(const float4*)&Wr[0] : z4;
    float4 wa1 = wok ? *(const float4*)&Wr[(size_t)8 * N] : z4;

    *(float4*)&Xs[0][fm * GXS + fh] =
        make_float4(to_tf32(xa0.x), to_tf32(xa0.y), to_tf32(xa0.z), to_tf32(xa0.w));
    *(float4*)&Xs[0][fm * GXS + fh + 4] =
        make_float4(to_tf32(xa1.x), to_tf32(xa1.y), to_tf32(xa1.z), to_tf32(xa1.w));
    *(float4*)&Ws[0][fk * GWS + fn] =
        make_float4(to_tf32(wa0.x), to_tf32(wa0.y), to_tf32(wa0.z), to_tf32(wa0.w));
    *(float4*)&Ws[0][(fk + 8) * GWS + fn] =
        make_float4(to_tf32(wa1.x), to_tf32(wa1.y), to_tf32(wa1.z), to_tf32(wa1.w));

    int p = 0;
    for (int k0 = 0; k0 < K; k0 += 16) {
        __syncthreads();  // stage p published; stage p^1 free
        const bool more = (k0 + 16) < K;
        if (more) {
            xa0 = *(const float4*)&Xr[k0 + 16];
            xa1 = *(const float4*)&Xr[k0 + 20];
            wa0 = wok ? *(const float4*)&Wr[(size_t)(k0 + 16) * N] : z4;
            wa1 = wok ? *(const float4*)&Wr[(size_t)(k0 + 24) * N] : z4;
        }
#pragma unroll
        for (int ks = 0; ks < 2; ks++) {
            unsigned a[4][4];
#pragma unroll
            for (int mt = 0; mt < 4; mt++)
                ldsm4(a[mt], &Xs[p][(wm + mt * 16 + ar) * GXS + ks * 8 + ac]);
#pragma unroll
            for (int nt = 0; nt < 4; nt++) {
                unsigned bb[2];
                bb[0] = fu(Ws[p][(ks * 8 + qd) * GWS + wn + nt * 8 + g]);
                bb[1] = fu(Ws[p][(ks * 8 + qd + 4) * GWS + wn + nt * 8 + g]);
#pragma unroll
                for (int mt = 0; mt < 4; mt++) mma8(acc[mt][nt], a[mt], bb);
            }
        }
        if (more) {
            int q = p ^ 1;
            *(float4*)&Xs[q][fm * GXS + fh] = make_float4(
                to_tf32(xa0.x), to_tf32(xa0.y), to_tf32(xa0.z), to_tf32(xa0.w));
            *(float4*)&Xs[q][fm * GXS + fh + 4] = make_float4(
                to_tf32(xa1.x), to_tf32(xa1.y), to_tf32(xa1.z), to_tf32(xa1.w));
            *(float4*)&Ws[q][fk * GWS + fn] = make_float4(
                to_tf32(wa0.x), to_tf32(wa0.y), to_tf32(wa0.z), to_tf32(wa0.w));
            *(float4*)&Ws[q][(fk + 8) * GWS + fn] = make_float4(
                to_tf32(wa1.x), to_tf32(wa1.y), to_tf32(wa1.z), to_tf32(wa1.w));
        }
        p ^= 1;
    }

#pragma unroll
    for (int mt = 0; mt < 4; mt++)
#pragma unroll
        for (int nt = 0; nt < 4; nt++) {
            int row = m0 + wm + mt * 16 + g;
            int col = n0 + wn + nt * 8 + 2 * qd;
            if (col < N) {
                *(float2*)&C[(size_t)row * N + col] =
                    make_float2(acc[mt][nt][0], acc[mt][nt][1]);
                *(float2*)&C[(size_t)(row + 8) * N + col] =
                    make_float2(acc[mt][nt][2], acc[mt][nt][3]);
            }
        }
}

__global__ __launch_bounds__(256, 2) void gemm_k(const float* __restrict__ X,
                                                 const float* __restrict__ W,
                                                 float* __restrict__ C, int N,
                                                 int K) {
    gemm3(X, W, C, N, K, blockIdx.y * 128, blockIdx.x * 128);
}

__global__ __launch_bounds__(256, 2) void proj_k(
    const float* __restrict__ q, const float* __restrict__ k,
    const float* __restrict__ v, const float* __restrict__ WAq,
    const float* __restrict__ WBq, const float* __restrict__ WAk,
    const float* __restrict__ WBk, const float* __restrict__ WAv,
    const float* __restrict__ WBv) {
    const int slot = blockIdx.x;
    const int slot_seg[8] = {0, 1, 1, 1, 2, 3, 4, 5};
    const int slot_n0[8] = {0, 0, 128, 256, 0, 0, 0, 0};
    const int seg = slot_seg[slot];
    const int seg_N[6] = {96, 384, 32, 128, 32, 128};
    const float* Xp = (seg < 2) ? q : (seg < 4) ? k : v;
    const float* Wp;
    float* Cp;
    switch (seg) {
        case 0: Wp = WAq; Cp = g_Aq; break;
        case 1: Wp = WBq; Cp = g_Bq; break;
        case 2: Wp = WAk; Cp = g_Ak; break;
        case 3: Wp = WBk; Cp = g_Bk; break;
        case 4: Wp = WAv; Cp = g_Av; break;
        default: Wp = WBv; Cp = g_Bv; break;
    }
    gemm3(Xp, Wp, Cp, seg_N[seg], ND, blockIdx.y * 128, slot_n0[slot]);
}

// ---------------------------------------------------------------------------
// RoPE + rank contraction -> qh/kh/vh (b,h,s,d), tf32-rounded.
// ---------------------------------------------------------------------------
__global__ __launch_bounds__(128) void mix_k() {
    const int t = blockIdx.x;
    const int b = t >> 11;
    const int s = t & (NS - 1);
    const int tid = threadIdx.x;

    __shared__ float sAq[96], sAk[32], sAv[32];
    __shared__ float sBq[384], sBk[128], sBv[128];

    if (tid < 96) sAq[tid] = g_Aq[t * 96 + tid];
    if (tid < 32) {
        sAk[tid] = g_Ak[t * 32 + tid];
        sAv[tid] = g_Av[t * 32 + tid];
    }
    for (int i = tid; i < 384; i += 128) sBq[i] = g_Bq[t * 384 + i];
    sBk[tid] = g_Bk[t * 128 + tid];
    sBv[tid] = g_Bv[t * 128 + tid];
    __syncthreads();

    for (int i = tid; i < (QR + RK) * 32; i += 128) {
        int r = i >> 5, dd = i & 31;
        float inv = (float)pow(10000.0, -(double)dd / 32.0);
        float c, sn;
        sincosf((float)s * inv, &sn, &c);
        float* base = (r < QR) ? &sBq[r * DKH] : &sBk[(r - QR) * DKH];
        float x1 = base[dd], x2 = base[dd + 32];
        base[dd] = x1 * c + x2 * sn;
        base[dd + 32] = -x1 * sn + x2 * c;
    }
    __syncthreads();

    const float qsc = 1.f / (6.f * 64.f);
    for (int i = tid; i < NH * DKH; i += 128) {
        int h = i >> 6, d = i & 63;
        float aq = 0.f;
#pragma unroll
        for (int r = 0; r < QR; r++) aq += sAq[h * QR + r] * sBq[r * DKH + d];
        size_t o = (((size_t)b * NH + h) * NS + s) * DKH + d;
        g_qh[o] = to_tf32(aq * qsc);
        g_kh[o] = to_tf32((sAk[h * RK] * sBk[d] + sAk[h * RK + 1] * sBk[DKH + d]) * 0.5f);
        g_vh[o] = to_tf32((sAv[h * RK] * sBv[d] + sAv[h * RK + 1] * sBv[DKH + d]) * 0.5f);
    }
}

// ---------------------------------------------------------------------------
// Causal flash attention: Q tile 128 (8 warps x 16 rows), KV tile 64,
// double-buffered K/V via cp.async, Q A-frags in registers (no Q smem),
// one barrier per kt. Dynamic smem = 2*(64*68 + 64*72)*4 = 71.7KB
// (> 48KB static cap -> MUST be dynamic) -> 2 blocks/SM.
// ---------------------------------------------------------------------------
#define KS_STR 68
#define VS_STR 72
#define KV_STAGE (64 * KS_STR + 64 * VS_STR)
#define ATT_SMEM (2 * KV_STAGE * (int)sizeof(float))

__global__ __launch_bounds__(256, 2) void attn_k() {
    extern __shared__ float sm[];

    const int qt = gridDim.x - 1 - blockIdx.x;  // heavy tiles first
    const int h = blockIdx.y, b = blockIdx.z;
    const int q0 = qt * 128;
    const int tid = threadIdx.x, lane = tid & 31, wid = tid >> 5;
    const int g = lane >> 2, qd = lane & 3;
    const size_t bh = ((size_t)b * NH + h) * NS * DKH;
    const int rb = wid * 16;
    const int ar = (lane & 7) + ((lane >> 3) & 1) * 8, ac = (lane >> 4) * 4;
    const int sl1 = (lane & 28) | (qd >> 1), sl2 = sl1 + 2;

    const int frow = tid >> 4, fc4 = (tid & 15) * 4;

    // Q A-fragments: 16 rows x 64 cols, straight from global (tf32 already)
    unsigned qa[8][4];
    {
        const float* Q0 = &g_qh[bh + (size_t)(q0 + rb + g) * DKH];
        const float* Q1 = Q0 + 8 * DKH;
#pragma unroll
        for (int ks = 0; ks < 8; ks++) {
            qa[ks][0] = fu(Q0[ks * 8 + qd]);
            qa[ks][1] = fu(Q1[ks * 8 + qd]);
            qa[ks][2] = fu(Q0[ks * 8 + qd + 4]);
            qa[ks][3] = fu(Q1[ks * 8 + qd + 4]);
        }
    }

    float m2[2] = {-1e30f, -1e30f};
    float l2[2] = {0.f, 0.f};
    float o[8][4];
#pragma unroll
    for (int nt = 0; nt < 8; nt++)
#pragma unroll
        for (int j = 0; j < 4; j++) o[nt][j] = 0.f;

    const int nkt = 2 * qt + 2;

    {  // prime stage 0 with tile kt=0
        float* Ksp = sm;
        float* Vsp = sm + 64 * KS_STR;
#pragma unroll
        for (int j = 0; j < 4; j++) {
            int row = frow + j * 16;
            size_t go = bh + (size_t)row * DKH + fc4;
            cpa16(&Ksp[row * KS_STR + fc4], &g_kh[go]);
            cpa16(&Vsp[row * VS_STR + fc4], &g_vh[go]);
        }
        CP_COMMIT();
    }

    for (int kt = 0; kt < nkt; kt++) {
        const int p = kt & 1;
        float* Ksp = sm + p * KV_STAGE;
        float* Vsp = Ksp + 64 * KS_STR;

        CP_WAIT0();
        __syncthreads();  // stage p visible; stage p^1 free (kt-1 compute done)

        if (kt + 1 < nkt) {
            float* Ksn = sm + (p ^ 1) * KV_STAGE;
            float* Vsn = Ksn + 64 * KS_STR;
#pragma unroll
            for (int j = 0; j < 4; j++) {
                int row = frow + j * 16;
                size_t go = bh + (size_t)((kt + 1) * 64 + row) * DKH + fc4;
                cpa16(&Ksn[row * KS_STR + fc4], &g_kh[go]);
                cpa16(&Vsn[row * VS_STR + fc4], &g_vh[go]);
            }
            CP_COMMIT();
        }

        if (!((kt == 2 * qt + 1) && (wid < 4))) {
            float s[8][4];
#pragma unroll
            for (int nt = 0; nt < 8; nt++)
#pragma unroll
                for (int j = 0; j < 4; j++) s[nt][j] = 0.f;
#pragma unroll
            for (int ks = 0; ks < 8; ks++) {
#pragma unroll
                for (int pp = 0; pp < 4; pp++) {
                    unsigned kb[4];
                    ldsm4(kb, &Ksp[(pp * 16 + ar) * KS_STR + ks * 8 + ac]);
                    unsigned b0[2] = {kb[0], kb[2]}, b1[2] = {kb[1], kb[3]};
                    mma8(s[2 * pp], qa[ks], b0);
                    mma8(s[2 * pp + 1], qa[ks], b1);
                }
            }

            if (kt >= 2 * qt) {
#pragma unroll
                for (int nt = 0; nt < 8; nt++)
#pragma unroll
                    for (int j = 0; j < 4; j++) {
                        int col = kt * 64 + nt * 8 + 2 * qd + (j & 1);
                        int row = q0 + rb + g + (j >> 1) * 8;
                        if (col > row) s[nt][j] = -1e30f;
                    }
            }

#pragma unroll
            for (int half = 0; half < 2; half++) {
                int jo = half * 2;
                float mx = -1e30f;
#pragma unroll
                for (int nt = 0; nt < 8; nt++)
                    mx = fmaxf(mx, fmaxf(s[nt][jo], s[nt][jo + 1]));
                mx = fmaxf(mx, __shfl_xor_sync(0xffffffffu, mx, 1));
                mx = fmaxf(mx, __shfl_xor_sync(0xffffffffu, mx, 2));
                float mn = fmaxf(m2[half], mx);
                float corr = __expf(m2[half] - mn);
                float sum = 0.f;
#pragma unroll
                for (int nt = 0; nt < 8; nt++) {
                    float e0 = __expf(s[nt][jo] - mn);
                    float e1 = __expf(s[nt][jo + 1] - mn);
                    sum += e0 + e1;
                    s[nt][jo] = e0;
                    s[nt][jo + 1] = e1;
                }
                sum += __shfl_xor_sync(0xffffffffu, sum, 1);
                sum += __shfl_xor_sync(0xffffffffu, sum, 2);
                l2[half] = l2[half] * corr + sum;
                m2[half] = mn;
#pragma unroll
                for (int nt = 0; nt < 8; nt++) {
                    o[nt][jo] *= corr;
                    o[nt][jo + 1] *= corr;
                }
            }

            // P C-frag -> A-frag by shuffle, then O += P V
#pragma unroll
            for (int kc = 0; kc < 8; kc++) {
                float c0 = s[kc][0], c1 = s[kc][1], c2 = s[kc][2], c3 = s[kc][3];
                float u0a = __shfl_sync(0xffffffffu, c0, sl1);
                float u0b = __shfl_sync(0xffffffffu, c1, sl1);
                float u1a = __shfl_sync(0xffffffffu, c2, sl1);
                float u1b = __shfl_sync(0xffffffffu, c3, sl1);
                float u2a = __shfl_sync(0xffffffffu, c0, sl2);
                float u2b = __shfl_sync(0xffffffffu, c1, sl2);
                float u3a = __shfl_sync(0xffffffffu, c2, sl2);
                float u3b = __shfl_sync(0xffffffffu, c3, sl2);
                bool od = qd & 1;
                unsigned a[4];
                a[0] = fu(to_tf32(od ? u0b : u0a));
                a[1] = fu(to_tf32(od ? u1b : u1a));
                a[2] = fu(to_tf32(od ? u2b : u2a));
                a[3] = fu(to_tf32(od ? u3b : u3a));
                int cb = kc * 8;
#pragma unroll
                for (int nt = 0; nt < 8; nt++) {
                    unsigned bb[2];
                    bb[0] = fu(Vsp[(cb + qd) * VS_STR + nt * 8 + g]);
                    bb[1] = fu(Vsp[(cb + qd + 4) * VS_STR + nt * 8 + g]);
                    mma8(o[nt], a, bb);
                }
            }
        }
    }

#pragma unroll
    for (int half = 0; half < 2; half++) {
        int jo = half * 2;
        float inv = 1.f / l2[half];
        int row = q0 + rb + g + half * 8;
        size_t ob = (((size_t)b * NS + row) * NH + h) * DKH;
#pragma unroll
        for (int nt = 0; nt < 8; nt++) {
            int col = nt * 8 + 2 * qd;
            *(float2*)&g_att[ob + col] =
                make_float2(o[nt][jo] * inv, o[nt][jo + 1] * inv);
        }
    }
}

// ---------------------------------------------------------------------------
extern "C" void kernel_launch(void* const* d_in, const int* in_sizes, int n_in,
                              void* d_out, int out_size) {
    (void)in_sizes; (void)n_in; (void)out_size;
    const float* q = (const float*)d_in[0];
    const float* k = (const float*)d_in[1];
    const float* v = (const float*)d_in[2];
    const float* W_Aq = (const float*)d_in[4];
    const float* W_Ak = (const float*)d_in[5];
    const float* W_Av = (const float*)d_in[6];
    const float* W_Bq = (const float*)d_in[7];
    const float* W_Bk = (const float*)d_in[8];
    const float* W_Bv = (const float*)d_in[9];
    const float* Wo = (const float*)d_in[10];

    float* pAtt;
    cudaGetSymbolAddress((void**)&pAtt, g_att);

    proj_k<<<dim3(8, 32), 256>>>(q, k, v, W_Aq, W_Bq, W_Ak, W_Bk, W_Av, W_Bv);
    mix_k<<<NT, 128>>>();
    cudaFuncSetAttribute(attn_k, cudaFuncAttributeMaxDynamicSharedMemorySize,
                         ATT_SMEM);
    attn_k<<<dim3(NS / 128, NH, NB), 256, ATT_SMEM>>>();
    gemm_k<<<dim3(ND / 128, NT / 128), 256>>>(pAtt, Wo, (float*)d_out, ND, ND);
}